// round 13
// baseline (speedup 1.0000x reference)
#include <cuda_runtime.h>
#include <math.h>

#define NN 4096
#define MM 4096
#define DD 64
#define W_EPS 0.1f
#define INV_EPS 10.0f
#define ITERS 10
#define RPS 128
#define SLABS (NN / RPS)            // 32

#define CT_STRIDE 132
#define CT_KH 32
#define SH_FLOATS (2 * CT_KH * CT_STRIDE)   // 8448 floats = 33792 B (>= 4096 for gs)

// ------------- static device scratch -------------
__device__ float d_C[(size_t)NN * MM];
__device__ float d_f[NN];
__device__ float d_g[MM];
__device__ float d_nx[NN];
__device__ float d_ny[MM];
__device__ float d_pm[SLABS * MM];
__device__ float d_ps[SLABS * MM];
__device__ double d_parts[2048];
__device__ unsigned g_barCount;
__device__ volatile unsigned g_barSense;

// ------------- grid barrier (sense-reversing; proven in R2) -------------
__device__ __forceinline__ void grid_barrier(unsigned target, int nb) {
    __syncthreads();
    if (threadIdx.x == 0) {
        __threadfence();
        if (atomicAdd(&g_barCount, 1u) == (unsigned)(nb - 1)) {
            g_barCount = 0u;
            __threadfence();
            g_barSense = target;
        } else {
            while ((int)(g_barSense - target) < 0) __nanosleep(32);
        }
        __threadfence();
    }
    __syncthreads();
}

// ------------- online-LSE helpers -------------
__device__ __forceinline__ void lse_merge(float& m1, float& s1, float m2, float s2) {
    float d = (m2 - m1) * INV_EPS;
    float e = __expf(-fabsf(d));
    if (d > 0.0f) { s1 = fmaf(s1, e, s2); m1 = m2; }
    else          { s1 = fmaf(s2, e, s1); }
}
__device__ __forceinline__ void lse_upd1(float& m, float& s, float v) {
    float d = (v - m) * INV_EPS;
    float e = __expf(-fabsf(d));
    bool up = d > 0.0f;
    s = up ? fmaf(s, e, 1.0f) : (s + e);
    m = up ? v : m;
}
__device__ __forceinline__ float4 f4sub(float4 a, float4 b) {
    return make_float4(a.x - b.x, a.y - b.y, a.z - b.z, a.w - b.w);
}
__device__ __forceinline__ float f4max(float4 a) {
    return fmaxf(fmaxf(a.x, a.y), fmaxf(a.z, a.w));
}
__device__ __forceinline__ float f4expsum(float4 a, float mn) {
    return __expf((a.x - mn) * INV_EPS) + __expf((a.y - mn) * INV_EPS)
         + __expf((a.z - mn) * INV_EPS) + __expf((a.w - mn) * INV_EPS);
}

__global__ void __launch_bounds__(256)
k_all(const float* __restrict__ x, const float* __restrict__ y,
      const float* __restrict__ p, const float* __restrict__ q,
      float* __restrict__ Pout, float* __restrict__ costslot, int nb)
{
    __shared__ float sh[SH_FLOATS];          // cost: xs|ys ; row: gs
    __shared__ float s_pm[16], s_ps[16];
    __shared__ double dred[8];
    const int t = threadIdx.x;
    const int b = blockIdx.x;
    const int lane = t & 31;
    const int warp = t >> 5;
    unsigned bt = g_barSense;

    // ========== phase 0: norms + g = 0 ==========
    {
        for (int j = b * 256 + t; j < MM; j += nb * 256) d_g[j] = 0.0f;
        const int nwarps = nb * 8;
        for (int row = b * 8 + warp; row < NN + MM; row += nwarps) {
            const float* src = (row < NN) ? (x + (size_t)row * DD)
                                          : (y + (size_t)(row - NN) * DD);
            float a = src[lane], c = src[lane + 32];
            float s = a * a + c * c;
            #pragma unroll
            for (int o = 16; o; o >>= 1) s += __shfl_xor_sync(0xffffffffu, s, o);
            if (lane == 0) { if (row < NN) d_nx[row] = s; else d_ny[row - NN] = s; }
        }
    }
    grid_barrier(++bt, nb);

    // ========== phase 1: C = nx + ny - 2 x.y (128x128 tiles, split 8x8, 2-phase K) ==========
    {
        float* xs = sh;
        float* ys = sh + CT_KH * CT_STRIDE;
        const int tx = t & 15, ty = t >> 4;
        for (int u = b; u < 1024; u += nb) {
            int rowBase = (u & 31) * 128, colBase = (u >> 5) * 128;
            float acc[8][8];
            #pragma unroll
            for (int r = 0; r < 8; r++)
                #pragma unroll
                for (int c = 0; c < 8; c++) acc[r][c] = 0.0f;

            #pragma unroll
            for (int ph = 0; ph < 2; ph++) {
                __syncthreads();                 // protect smem reuse (tiles & phases)
                #pragma unroll
                for (int k2 = 0; k2 < 4; k2++) {
                    int idx = t + 256 * k2;
                    int rid = idx >> 3;
                    int d4 = (idx & 7) << 2;
                    float4 v = *(const float4*)(x + (size_t)(rowBase + rid) * DD + ph * CT_KH + d4);
                    xs[(d4 + 0) * CT_STRIDE + rid] = v.x;
                    xs[(d4 + 1) * CT_STRIDE + rid] = v.y;
                    xs[(d4 + 2) * CT_STRIDE + rid] = v.z;
                    xs[(d4 + 3) * CT_STRIDE + rid] = v.w;
                }
                #pragma unroll
                for (int k2 = 0; k2 < 4; k2++) {
                    int idx = t + 256 * k2;
                    int cid = idx >> 3;
                    int d4 = (idx & 7) << 2;
                    float4 v = *(const float4*)(y + (size_t)(colBase + cid) * DD + ph * CT_KH + d4);
                    ys[(d4 + 0) * CT_STRIDE + cid] = v.x;
                    ys[(d4 + 1) * CT_STRIDE + cid] = v.y;
                    ys[(d4 + 2) * CT_STRIDE + cid] = v.z;
                    ys[(d4 + 3) * CT_STRIDE + cid] = v.w;
                }
                __syncthreads();

                #pragma unroll 8
                for (int d = 0; d < CT_KH; d++) {
                    const float* xr = xs + d * CT_STRIDE;
                    const float* yc = ys + d * CT_STRIDE;
                    float4 a0 = *(const float4*)(xr + (ty << 2));
                    float4 a1 = *(const float4*)(xr + (ty << 2) + 64);
                    float4 b0 = *(const float4*)(yc + (tx << 2));
                    float4 b1 = *(const float4*)(yc + (tx << 2) + 64);
                    float av[8] = {a0.x, a0.y, a0.z, a0.w, a1.x, a1.y, a1.z, a1.w};
                    float bv[8] = {b0.x, b0.y, b0.z, b0.w, b1.x, b1.y, b1.z, b1.w};
                    #pragma unroll
                    for (int r = 0; r < 8; r++)
                        #pragma unroll
                        for (int c = 0; c < 8; c++)
                            acc[r][c] = fmaf(av[r], bv[c], acc[r][c]);
                }
            }

            float4 nyA = *(const float4*)(d_ny + colBase + (tx << 2));
            float4 nyB = *(const float4*)(d_ny + colBase + (tx << 2) + 64);
            #pragma unroll
            for (int rg = 0; rg < 2; rg++) {
                #pragma unroll
                for (int r4 = 0; r4 < 4; r4++) {
                    int r = rg * 4 + r4;
                    int row = rowBase + (ty << 2) + rg * 64 + r4;
                    float nxr = d_nx[row];
                    float4 oA, oB;
                    oA.x = nxr + nyA.x - 2.0f * acc[r][0];
                    oA.y = nxr + nyA.y - 2.0f * acc[r][1];
                    oA.z = nxr + nyA.z - 2.0f * acc[r][2];
                    oA.w = nxr + nyA.w - 2.0f * acc[r][3];
                    oB.x = nxr + nyB.x - 2.0f * acc[r][4];
                    oB.y = nxr + nyB.y - 2.0f * acc[r][5];
                    oB.z = nxr + nyB.z - 2.0f * acc[r][6];
                    oB.w = nxr + nyB.w - 2.0f * acc[r][7];
                    float* dst = d_C + (size_t)row * MM + colBase + (tx << 2);
                    *(float4*)dst = oA;
                    *(float4*)(dst + 64) = oB;
                }
            }
        }
    }
    grid_barrier(++bt, nb);

    // ========== phase 2: Sinkhorn iterations ==========
    const int nwarps = nb * 8;
    const int gw = b * 8 + warp;

    for (int it = 0; it < ITERS; it++) {
        // ---- row pass: g staged to smem once per block; 2 rows per step ----
        {
            #pragma unroll
            for (int k2 = 0; k2 < 4; k2++) {
                int j = (t + 256 * k2) * 4;
                *(float4*)(sh + j) = *(const float4*)(d_g + j);
            }
            __syncthreads();
            for (int pr = b; pr < NN / 2; pr += nb) {
                int r0 = pr * 2;
                const float* C0 = d_C + (size_t)r0 * MM;
                const float* C1 = C0 + MM;
                float4 v0[4], v1[4];
                #pragma unroll
                for (int w = 0; w < 4; w++) {
                    int j = (t + 256 * w) * 4;
                    float4 g4 = *(const float4*)(sh + j);
                    float4 c0 = *(const float4*)(C0 + j);
                    float4 c1 = *(const float4*)(C1 + j);
                    v0[w] = f4sub(g4, c0);
                    v1[w] = f4sub(g4, c1);
                }
                float m0 = fmaxf(fmaxf(f4max(v0[0]), f4max(v0[1])), fmaxf(f4max(v0[2]), f4max(v0[3])));
                float m1 = fmaxf(fmaxf(f4max(v1[0]), f4max(v1[1])), fmaxf(f4max(v1[2]), f4max(v1[3])));
                float s0 = f4expsum(v0[0], m0) + f4expsum(v0[1], m0) + f4expsum(v0[2], m0) + f4expsum(v0[3], m0);
                float s1 = f4expsum(v1[0], m1) + f4expsum(v1[1], m1) + f4expsum(v1[2], m1) + f4expsum(v1[3], m1);
                #pragma unroll
                for (int o = 16; o; o >>= 1) {
                    float mo = __shfl_down_sync(0xffffffffu, m0, o);
                    float so = __shfl_down_sync(0xffffffffu, s0, o);
                    lse_merge(m0, s0, mo, so);
                    mo = __shfl_down_sync(0xffffffffu, m1, o);
                    so = __shfl_down_sync(0xffffffffu, s1, o);
                    lse_merge(m1, s1, mo, so);
                }
                if (lane == 0) {
                    s_pm[warp] = m0;     s_ps[warp] = s0;
                    s_pm[8 + warp] = m1; s_ps[8 + warp] = s1;
                }
                __syncthreads();
                if (warp == 0) {
                    float mm = s_pm[lane & 15], ss = s_ps[lane & 15];
                    #pragma unroll
                    for (int o = 4; o; o >>= 1) {
                        float mo = __shfl_down_sync(0xffffffffu, mm, o, 8);
                        float so = __shfl_down_sync(0xffffffffu, ss, o, 8);
                        lse_merge(mm, ss, mo, so);
                    }
                    if (lane == 0) d_f[r0]     = W_EPS * __logf(p[r0])     - mm - W_EPS * __logf(ss);
                    if (lane == 8) d_f[r0 + 1] = W_EPS * __logf(p[r0 + 1]) - mm - W_EPS * __logf(ss);
                }
                __syncthreads();
            }
        }
        grid_barrier(++bt, nb);

        // ---- column partials: warp per (slab, 32-col group), 4 ILP chains ----
        for (int u = gw; u < SLABS * (MM / 32); u += nwarps) {
            int slab = u >> 7;
            int col = ((u & 127) << 5) + lane;
            const float* Cp = d_C + (size_t)slab * RPS * MM + col;
            const float* fp = d_f + slab * RPS;
            float m0 = -3.4e38f, s0 = 0.0f, m1 = -3.4e38f, s1 = 0.0f;
            float m2 = -3.4e38f, s2 = 0.0f, m3 = -3.4e38f, s3 = 0.0f;
            #pragma unroll 8
            for (int k = 0; k < RPS / 4; k++) {
                int r = k * 4;
                float c0 = Cp[(size_t)(r + 0) * MM];
                float c1 = Cp[(size_t)(r + 1) * MM];
                float c2 = Cp[(size_t)(r + 2) * MM];
                float c3 = Cp[(size_t)(r + 3) * MM];
                lse_upd1(m0, s0, fp[r + 0] - c0);
                lse_upd1(m1, s1, fp[r + 1] - c1);
                lse_upd1(m2, s2, fp[r + 2] - c2);
                lse_upd1(m3, s3, fp[r + 3] - c3);
            }
            lse_merge(m0, s0, m1, s1);
            lse_merge(m2, s2, m3, s3);
            lse_merge(m0, s0, m2, s2);
            d_pm[slab * MM + col] = m0;
            d_ps[slab * MM + col] = s0;
        }
        grid_barrier(++bt, nb);

        // ---- column finalize ----
        for (int j = b * 256 + t; j < MM; j += nb * 256) {
            float m0 = -3.4e38f, s0 = 0.0f, m1 = -3.4e38f, s1 = 0.0f;
            float m2 = -3.4e38f, s2 = 0.0f, m3 = -3.4e38f, s3 = 0.0f;
            #pragma unroll
            for (int k = 0; k < SLABS / 4; k++) {
                int k4 = k * 4;
                lse_merge(m0, s0, d_pm[(k4 + 0) * MM + j], d_ps[(k4 + 0) * MM + j]);
                lse_merge(m1, s1, d_pm[(k4 + 1) * MM + j], d_ps[(k4 + 1) * MM + j]);
                lse_merge(m2, s2, d_pm[(k4 + 2) * MM + j], d_ps[(k4 + 2) * MM + j]);
                lse_merge(m3, s3, d_pm[(k4 + 3) * MM + j], d_ps[(k4 + 3) * MM + j]);
            }
            lse_merge(m0, s0, m1, s1);
            lse_merge(m2, s2, m3, s3);
            lse_merge(m0, s0, m2, s2);
            d_g[j] = W_EPS * __logf(q[j]) - m0 - W_EPS * __logf(s0);
        }
        grid_barrier(++bt, nb);
    }

    // ========== phase 3: P = exp(S), cost partials ==========
    {
        double csum = 0.0;
        const int gsz = nb * 256;
        const int NV4 = (NN * MM) / 4;
        #pragma unroll 4
        for (int v4 = b * 256 + t; v4 < NV4; v4 += gsz) {
            int base = v4 * 4;
            int i = base >> 12;
            int j = base & (MM - 1);
            float4 c4 = *(const float4*)(d_C + (size_t)base);
            float fi = d_f[i];
            float4 g4 = *(const float4*)(d_g + j);
            float p0 = __expf((fi + g4.x - c4.x) * INV_EPS);
            float p1 = __expf((fi + g4.y - c4.y) * INV_EPS);
            float p2 = __expf((fi + g4.z - c4.z) * INV_EPS);
            float p3 = __expf((fi + g4.w - c4.w) * INV_EPS);
            if (Pout) {
                Pout[base + 0] = p0; Pout[base + 1] = p1;
                Pout[base + 2] = p2; Pout[base + 3] = p3;
            }
            csum += (double)(p0 * c4.x + p1 * c4.y + p2 * c4.z + p3 * c4.w);
        }
        #pragma unroll
        for (int o = 16; o; o >>= 1) csum += __shfl_xor_sync(0xffffffffu, csum, o);
        if (lane == 0) dred[warp] = csum;
        __syncthreads();
        if (t == 0) {
            double sb = 0.0;
            #pragma unroll
            for (int k2 = 0; k2 < 8; k2++) sb += dred[k2];
            d_parts[b] = sb;
        }
    }
    grid_barrier(++bt, nb);

    if (b == 0 && costslot) {
        double s = 0.0;
        for (int k2 = t; k2 < nb; k2 += 256) s += d_parts[k2];
        // reuse sh as a double staging area (phase-exclusive)
        double* fin = (double*)sh;
        fin[t] = s;
        __syncthreads();
        if (t == 0) {
            double tot = 0.0;
            for (int k2 = 0; k2 < 256; k2++) tot += fin[k2];
            costslot[0] = (float)tot;
        }
    }
}

// ================= host launch =================
extern "C" void kernel_launch(void* const* d_in, const int* in_sizes, int n_in,
                              void* d_out, int out_size) {
    const float* x = (const float*)d_in[0];
    const float* y = (const float*)d_in[1];
    const float* p = (const float*)d_in[2];
    const float* q = (const float*)d_in[3];
    (void)in_sizes; (void)n_in;

    float* out = (float*)d_out;
    float* costslot = nullptr;
    float* Pout = nullptr;
    const long long total = (long long)NN * MM;
    if ((long long)out_size >= total + 1) { costslot = out; Pout = out + 1; }
    else if ((long long)out_size >= total) { Pout = out; }
    else { costslot = out; }

    int dev = 0;
    cudaGetDevice(&dev);
    cudaDeviceProp prop;
    cudaGetDeviceProperties(&prop, dev);
    int occ = 0;
    cudaOccupancyMaxActiveBlocksPerMultiprocessor(&occ, k_all, 256, 0);
    if (occ < 1) occ = 1;
    long long nb = (long long)prop.multiProcessorCount * occ;
    if (nb > 1024) nb = 1024;

    k_all<<<(int)nb, 256>>>(x, y, p, q, Pout, costslot, (int)nb);
}

// round 14
// speedup vs baseline: 1.0810x; 1.0810x over previous
#include <cuda_runtime.h>
#include <math.h>

#define NN 4096
#define MM 4096
#define DD 64
#define W_EPS 0.1f
#define INV_EPS 10.0f
#define ITERS 10
#define RPS 128
#define SLABS (NN / RPS)            // 32  (exact col pass, iter 1)

#define FS 16                       // fused slab rows
#define FSLABS (NN / FS)            // 256 fused slabs

#define CT_STRIDE 132
#define CT_KH 32

// ------------- static device scratch -------------
__device__ float d_C[(size_t)NN * MM];
__device__ float d_f[NN];
__device__ float d_g[MM];
__device__ float d_nx[NN];
__device__ float d_ny[MM];
__device__ float d_pm[SLABS * MM];
__device__ float d_ps[SLABS * MM];
__device__ float d_colsum[FSLABS * MM];     // 4 MB fused column partial sums
__device__ double d_parts[2048];

// ------------- online-LSE helpers -------------
__device__ __forceinline__ void lse_merge(float& m1, float& s1, float m2, float s2) {
    float d = (m2 - m1) * INV_EPS;
    float e = __expf(-fabsf(d));
    if (d > 0.0f) { s1 = fmaf(s1, e, s2); m1 = m2; }
    else          { s1 = fmaf(s2, e, s1); }
}
__device__ __forceinline__ void lse_upd1(float& m, float& s, float v) {
    float d = (v - m) * INV_EPS;
    float e = __expf(-fabsf(d));
    bool up = d > 0.0f;
    s = up ? fmaf(s, e, 1.0f) : (s + e);
    m = up ? v : m;
}
__device__ __forceinline__ float4 f4sub(float4 a, float4 b) {
    return make_float4(a.x - b.x, a.y - b.y, a.z - b.z, a.w - b.w);
}
__device__ __forceinline__ float f4max(float4 a) {
    return fmaxf(fmaxf(a.x, a.y), fmaxf(a.z, a.w));
}
__device__ __forceinline__ float f4expsum(float4 a, float mn) {
    return __expf((a.x - mn) * INV_EPS) + __expf((a.y - mn) * INV_EPS)
         + __expf((a.z - mn) * INV_EPS) + __expf((a.w - mn) * INV_EPS);
}

// ================= prep: norms + g = 0 =================
__global__ void k_prep(const float* __restrict__ x, const float* __restrict__ y) {
    int gtid = blockIdx.x * 256 + threadIdx.x;
    if (gtid < MM) d_g[gtid] = 0.0f;
    int lane = threadIdx.x & 31;
    int row = gtid >> 5;
    const float* src = (row < NN) ? (x + (size_t)row * DD)
                                  : (y + (size_t)(row - NN) * DD);
    float a = src[lane], c = src[lane + 32];
    float s = a * a + c * c;
    #pragma unroll
    for (int o = 16; o; o >>= 1) s += __shfl_xor_sync(0xffffffffu, s, o);
    if (lane == 0) { if (row < NN) d_nx[row] = s; else d_ny[row - NN] = s; }
}

// ====== cost: C = nx + ny - 2 x.y (128x128 tile, split 8x8 micro, 2-phase K) ======
__global__ void __launch_bounds__(256)
k_cost(const float* __restrict__ x, const float* __restrict__ y) {
    __shared__ float xs[CT_KH * CT_STRIDE];
    __shared__ float ys[CT_KH * CT_STRIDE];
    const int t = threadIdx.x;
    const int tx = t & 15, ty = t >> 4;
    const int rowBase = blockIdx.y * 128, colBase = blockIdx.x * 128;

    float acc[8][8];
    #pragma unroll
    for (int r = 0; r < 8; r++)
        #pragma unroll
        for (int c = 0; c < 8; c++) acc[r][c] = 0.0f;

    #pragma unroll
    for (int ph = 0; ph < 2; ph++) {
        if (ph) __syncthreads();
        #pragma unroll
        for (int k2 = 0; k2 < 4; k2++) {
            int idx = t + 256 * k2;
            int rid = idx >> 3;
            int d4 = (idx & 7) << 2;
            float4 v = *(const float4*)(x + (size_t)(rowBase + rid) * DD + ph * CT_KH + d4);
            xs[(d4 + 0) * CT_STRIDE + rid] = v.x;
            xs[(d4 + 1) * CT_STRIDE + rid] = v.y;
            xs[(d4 + 2) * CT_STRIDE + rid] = v.z;
            xs[(d4 + 3) * CT_STRIDE + rid] = v.w;
        }
        #pragma unroll
        for (int k2 = 0; k2 < 4; k2++) {
            int idx = t + 256 * k2;
            int cid = idx >> 3;
            int d4 = (idx & 7) << 2;
            float4 v = *(const float4*)(y + (size_t)(colBase + cid) * DD + ph * CT_KH + d4);
            ys[(d4 + 0) * CT_STRIDE + cid] = v.x;
            ys[(d4 + 1) * CT_STRIDE + cid] = v.y;
            ys[(d4 + 2) * CT_STRIDE + cid] = v.z;
            ys[(d4 + 3) * CT_STRIDE + cid] = v.w;
        }
        __syncthreads();

        #pragma unroll 8
        for (int d = 0; d < CT_KH; d++) {
            const float* xr = xs + d * CT_STRIDE;
            const float* yc = ys + d * CT_STRIDE;
            float4 a0 = *(const float4*)(xr + (ty << 2));
            float4 a1 = *(const float4*)(xr + (ty << 2) + 64);
            float4 b0 = *(const float4*)(yc + (tx << 2));
            float4 b1 = *(const float4*)(yc + (tx << 2) + 64);
            float av[8] = {a0.x, a0.y, a0.z, a0.w, a1.x, a1.y, a1.z, a1.w};
            float bv[8] = {b0.x, b0.y, b0.z, b0.w, b1.x, b1.y, b1.z, b1.w};
            #pragma unroll
            for (int r = 0; r < 8; r++)
                #pragma unroll
                for (int c = 0; c < 8; c++)
                    acc[r][c] = fmaf(av[r], bv[c], acc[r][c]);
        }
    }

    float4 nyA = *(const float4*)(d_ny + colBase + (tx << 2));
    float4 nyB = *(const float4*)(d_ny + colBase + (tx << 2) + 64);
    #pragma unroll
    for (int rg = 0; rg < 2; rg++) {
        #pragma unroll
        for (int r4 = 0; r4 < 4; r4++) {
            int r = rg * 4 + r4;
            int row = rowBase + (ty << 2) + rg * 64 + r4;
            float nxr = d_nx[row];
            float4 oA, oB;
            oA.x = nxr + nyA.x - 2.0f * acc[r][0];
            oA.y = nxr + nyA.y - 2.0f * acc[r][1];
            oA.z = nxr + nyA.z - 2.0f * acc[r][2];
            oA.w = nxr + nyA.w - 2.0f * acc[r][3];
            oB.x = nxr + nyB.x - 2.0f * acc[r][4];
            oB.y = nxr + nyB.y - 2.0f * acc[r][5];
            oB.z = nxr + nyB.z - 2.0f * acc[r][6];
            oB.w = nxr + nyB.w - 2.0f * acc[r][7];
            float* dst = d_C + (size_t)row * MM + colBase + (tx << 2);
            *(float4*)dst = oA;
            *(float4*)(dst + 64) = oB;
        }
    }
}

// ====== iter-1 exact kernels (unchanged from 375us base) ======
__global__ void __launch_bounds__(256)
k_row(const float* __restrict__ p) {
    __shared__ float s_pm[16], s_ps[16];
    const int t = threadIdx.x;
    const int lane = t & 31;
    const int warp = t >> 5;
    const int r0 = blockIdx.x * 2;
    const float* C0 = d_C + (size_t)r0 * MM;
    const float* C1 = C0 + MM;

    float4 v0[4], v1[4];
    #pragma unroll
    for (int w = 0; w < 4; w++) {
        int j = (t + 256 * w) * 4;
        float4 g4 = *(const float4*)(d_g + j);
        float4 c0 = *(const float4*)(C0 + j);
        float4 c1 = *(const float4*)(C1 + j);
        v0[w] = f4sub(g4, c0);
        v1[w] = f4sub(g4, c1);
    }
    float m0 = fmaxf(fmaxf(f4max(v0[0]), f4max(v0[1])), fmaxf(f4max(v0[2]), f4max(v0[3])));
    float m1 = fmaxf(fmaxf(f4max(v1[0]), f4max(v1[1])), fmaxf(f4max(v1[2]), f4max(v1[3])));
    float s0 = f4expsum(v0[0], m0) + f4expsum(v0[1], m0) + f4expsum(v0[2], m0) + f4expsum(v0[3], m0);
    float s1 = f4expsum(v1[0], m1) + f4expsum(v1[1], m1) + f4expsum(v1[2], m1) + f4expsum(v1[3], m1);

    #pragma unroll
    for (int o = 16; o; o >>= 1) {
        float mo = __shfl_down_sync(0xffffffffu, m0, o);
        float so = __shfl_down_sync(0xffffffffu, s0, o);
        lse_merge(m0, s0, mo, so);
        mo = __shfl_down_sync(0xffffffffu, m1, o);
        so = __shfl_down_sync(0xffffffffu, s1, o);
        lse_merge(m1, s1, mo, so);
    }
    if (lane == 0) {
        s_pm[warp] = m0;     s_ps[warp] = s0;
        s_pm[8 + warp] = m1; s_ps[8 + warp] = s1;
    }
    __syncthreads();
    if (warp == 0) {
        float mm = s_pm[lane & 15], ss = s_ps[lane & 15];
        #pragma unroll
        for (int o = 4; o; o >>= 1) {
            float mo = __shfl_down_sync(0xffffffffu, mm, o, 8);
            float so = __shfl_down_sync(0xffffffffu, ss, o, 8);
            lse_merge(mm, ss, mo, so);
        }
        if (lane == 0) d_f[r0]     = W_EPS * __logf(p[r0])     - mm - W_EPS * __logf(ss);
        if (lane == 8) d_f[r0 + 1] = W_EPS * __logf(p[r0 + 1]) - mm - W_EPS * __logf(ss);
    }
}

__global__ void __launch_bounds__(256)
k_colpart() {
    const int lane = threadIdx.x & 31;
    const int warp = threadIdx.x >> 5;
    const int u = blockIdx.x * 8 + warp;
    const int slab = u >> 7;
    const int col = ((u & 127) << 5) + lane;
    const float* Cp = d_C + (size_t)slab * RPS * MM + col;
    const float* fp = d_f + slab * RPS;

    float m0 = -3.4e38f, s0 = 0.0f, m1 = -3.4e38f, s1 = 0.0f;
    float m2 = -3.4e38f, s2 = 0.0f, m3 = -3.4e38f, s3 = 0.0f;
    #pragma unroll 8
    for (int k = 0; k < RPS / 4; k++) {
        int r = k * 4;
        float c0 = Cp[(size_t)(r + 0) * MM];
        float c1 = Cp[(size_t)(r + 1) * MM];
        float c2 = Cp[(size_t)(r + 2) * MM];
        float c3 = Cp[(size_t)(r + 3) * MM];
        lse_upd1(m0, s0, fp[r + 0] - c0);
        lse_upd1(m1, s1, fp[r + 1] - c1);
        lse_upd1(m2, s2, fp[r + 2] - c2);
        lse_upd1(m3, s3, fp[r + 3] - c3);
    }
    lse_merge(m0, s0, m1, s1);
    lse_merge(m2, s2, m3, s3);
    lse_merge(m0, s0, m2, s2);
    d_pm[slab * MM + col] = m0;
    d_ps[slab * MM + col] = s0;
}

__global__ void __launch_bounds__(256)
k_colfin(const float* __restrict__ q) {
    int j = blockIdx.x * 256 + threadIdx.x;
    float m0 = -3.4e38f, s0 = 0.0f, m1 = -3.4e38f, s1 = 0.0f;
    float m2 = -3.4e38f, s2 = 0.0f, m3 = -3.4e38f, s3 = 0.0f;
    #pragma unroll
    for (int k = 0; k < SLABS / 4; k++) {
        int k4 = k * 4;
        lse_merge(m0, s0, d_pm[(k4 + 0) * MM + j], d_ps[(k4 + 0) * MM + j]);
        lse_merge(m1, s1, d_pm[(k4 + 1) * MM + j], d_ps[(k4 + 1) * MM + j]);
        lse_merge(m2, s2, d_pm[(k4 + 2) * MM + j], d_ps[(k4 + 2) * MM + j]);
        lse_merge(m3, s3, d_pm[(k4 + 3) * MM + j], d_ps[(k4 + 3) * MM + j]);
    }
    lse_merge(m0, s0, m1, s1);
    lse_merge(m2, s2, m3, s3);
    lse_merge(m0, s0, m2, s2);
    d_g[j] = W_EPS * __logf(q[j]) - m0 - W_EPS * __logf(s0);
}

// ====== fused row+col sweep (iters 2..10): ONE pass over C ======
// Block = slab of FS=16 rows (8 pairs). For each row: exact row LSE -> f_i; column
// contribution is p_i*e_ij/S_i (algebraically = exp((f_i+g_j-C_ij)/eps)), summed into
// slab-private per-thread accumulators. No second C read, no extra per-element exp.
__global__ void __launch_bounds__(256)
k_rowcol(const float* __restrict__ p) {
    __shared__ float gs[MM];                 // 16 KB staged g
    __shared__ float rm[16], rs[16];
    const int t = threadIdx.x;
    const int lane = t & 31;
    const int warp = t >> 5;
    const int slab = blockIdx.x;
    const int rbase = slab * FS;

    #pragma unroll
    for (int k = 0; k < 4; k++) {
        int j = (t + 256 * k) * 4;
        *(float4*)(gs + j) = *(const float4*)(d_g + j);
    }
    __syncthreads();

    float acc[16];
    #pragma unroll
    for (int k = 0; k < 16; k++) acc[k] = 0.0f;

    for (int pr = 0; pr < FS / 2; pr++) {
        int r0 = rbase + pr * 2;
        const float* C0 = d_C + (size_t)r0 * MM;
        const float* C1 = C0 + MM;
        float e0[16], e1[16];

        // v into e arrays, track per-thread max
        float ml0 = -3.4e38f, ml1 = -3.4e38f;
        #pragma unroll
        for (int w = 0; w < 4; w++) {
            int j = (t + 256 * w) * 4;
            float4 g4 = *(const float4*)(gs + j);
            float4 c0 = *(const float4*)(C0 + j);
            float4 c1 = *(const float4*)(C1 + j);
            float4 a = f4sub(g4, c0);
            float4 bb = f4sub(g4, c1);
            e0[4 * w + 0] = a.x; e0[4 * w + 1] = a.y; e0[4 * w + 2] = a.z; e0[4 * w + 3] = a.w;
            e1[4 * w + 0] = bb.x; e1[4 * w + 1] = bb.y; e1[4 * w + 2] = bb.z; e1[4 * w + 3] = bb.w;
            ml0 = fmaxf(ml0, f4max(a));
            ml1 = fmaxf(ml1, f4max(bb));
        }
        // exp in place relative to thread-local max
        float sl0 = 0.0f, sl1 = 0.0f;
        #pragma unroll
        for (int k = 0; k < 16; k++) {
            e0[k] = __expf((e0[k] - ml0) * INV_EPS); sl0 += e0[k];
            e1[k] = __expf((e1[k] - ml1) * INV_EPS); sl1 += e1[k];
        }
        // butterfly warp merge -> all lanes hold warp (m,s)
        float m0 = ml0, s0 = sl0, m1 = ml1, s1 = sl1;
        #pragma unroll
        for (int o = 16; o; o >>= 1) {
            float mo = __shfl_xor_sync(0xffffffffu, m0, o);
            float so = __shfl_xor_sync(0xffffffffu, s0, o);
            lse_merge(m0, s0, mo, so);
            mo = __shfl_xor_sync(0xffffffffu, m1, o);
            so = __shfl_xor_sync(0xffffffffu, s1, o);
            lse_merge(m1, s1, mo, so);
        }
        if (lane == 0) { rm[warp] = m0; rs[warp] = s0; rm[8 + warp] = m1; rs[8 + warp] = s1; }
        __syncthreads();
        // every thread merges the 8 warp results (redundant, avoids broadcast sync)
        float M0 = rm[0], S0 = rs[0], M1 = rm[8], S1 = rs[8];
        #pragma unroll
        for (int k = 1; k < 8; k++) {
            lse_merge(M0, S0, rm[k], rs[k]);
            lse_merge(M1, S1, rm[8 + k], rs[8 + k]);
        }
        float pa = __ldg(p + r0), pb = __ldg(p + r0 + 1);
        if (t == 0) {
            d_f[r0]     = W_EPS * __logf(pa) - M0 - W_EPS * __logf(S0);
            d_f[r0 + 1] = W_EPS * __logf(pb) - M1 - W_EPS * __logf(S1);
        }
        // column contribution: p_i/S_i * exp((ml - M)/eps) * e_local
        float sc0 = pa * __expf((ml0 - M0) * INV_EPS) / S0;
        float sc1 = pb * __expf((ml1 - M1) * INV_EPS) / S1;
        #pragma unroll
        for (int k = 0; k < 16; k++)
            acc[k] = fmaf(sc0, e0[k], fmaf(sc1, e1[k], acc[k]));
        __syncthreads();   // WAR on rm/rs
    }

    float* dst = d_colsum + (size_t)slab * MM;
    #pragma unroll
    for (int w = 0; w < 4; w++) {
        int j = (t + 256 * w) * 4;
        float4 o = make_float4(acc[4 * w + 0], acc[4 * w + 1], acc[4 * w + 2], acc[4 * w + 3]);
        *(float4*)(dst + j) = o;
    }
}

// colfin for fused iters: g_new = eps*logq + g_old - eps*log(sum_slabs A)
__global__ void __launch_bounds__(256)
k_colfin2(const float* __restrict__ q) {
    int j = blockIdx.x * 256 + threadIdx.x;   // 16 blocks
    float a0 = 0.0f, a1 = 0.0f, a2 = 0.0f, a3 = 0.0f;
    #pragma unroll 8
    for (int s = 0; s < FSLABS; s += 4) {
        a0 += d_colsum[(size_t)(s + 0) * MM + j];
        a1 += d_colsum[(size_t)(s + 1) * MM + j];
        a2 += d_colsum[(size_t)(s + 2) * MM + j];
        a3 += d_colsum[(size_t)(s + 3) * MM + j];
    }
    float A = (a0 + a1) + (a2 + a3);
    d_g[j] = W_EPS * __logf(q[j]) + d_g[j] - W_EPS * __logf(A);
}

// ================= final: P = exp(S), cost partials =================
__global__ void __launch_bounds__(256)
k_final(float* __restrict__ Pout, int writeP) {
    __shared__ double dred[8];
    const int gsz = 2048 * 256;
    const int gtid = blockIdx.x * 256 + threadIdx.x;
    const int NV4 = (NN * MM) / 4;
    double csum = 0.0;
    #pragma unroll 4
    for (int v4 = gtid; v4 < NV4; v4 += gsz) {
        int base = v4 * 4;
        int i = base >> 12;
        int j = base & (MM - 1);
        float4 c4 = *(const float4*)(d_C + (size_t)base);
        float fi = d_f[i];
        float4 g4 = *(const float4*)(d_g + j);
        float p0 = __expf((fi + g4.x - c4.x) * INV_EPS);
        float p1 = __expf((fi + g4.y - c4.y) * INV_EPS);
        float p2 = __expf((fi + g4.z - c4.z) * INV_EPS);
        float p3 = __expf((fi + g4.w - c4.w) * INV_EPS);
        if (writeP) {
            Pout[base + 0] = p0; Pout[base + 1] = p1;
            Pout[base + 2] = p2; Pout[base + 3] = p3;
        }
        csum += (double)(p0 * c4.x + p1 * c4.y + p2 * c4.z + p3 * c4.w);
    }
    #pragma unroll
    for (int o = 16; o; o >>= 1) csum += __shfl_xor_sync(0xffffffffu, csum, o);
    if ((threadIdx.x & 31) == 0) dred[threadIdx.x >> 5] = csum;
    __syncthreads();
    if (threadIdx.x == 0) {
        double sb = 0.0;
        #pragma unroll
        for (int k2 = 0; k2 < 8; k2++) sb += dred[k2];
        d_parts[blockIdx.x] = sb;
    }
}

__global__ void k_costfin(float* __restrict__ costslot) {
    __shared__ double fin[256];
    int t = threadIdx.x;
    double s = 0.0;
    for (int k2 = t; k2 < 2048; k2 += 256) s += d_parts[k2];
    fin[t] = s;
    __syncthreads();
    if (t == 0) {
        double tot = 0.0;
        for (int k2 = 0; k2 < 256; k2++) tot += fin[k2];
        costslot[0] = (float)tot;
    }
}

// ================= host launch =================
extern "C" void kernel_launch(void* const* d_in, const int* in_sizes, int n_in,
                              void* d_out, int out_size) {
    const float* x = (const float*)d_in[0];
    const float* y = (const float*)d_in[1];
    const float* p = (const float*)d_in[2];
    const float* q = (const float*)d_in[3];
    (void)in_sizes; (void)n_in;

    float* out = (float*)d_out;
    float* costslot = nullptr;
    float* Pout = nullptr;
    const long long total = (long long)NN * MM;
    if ((long long)out_size >= total + 1) { costslot = out; Pout = out + 1; }
    else if ((long long)out_size >= total) { Pout = out; }
    else { costslot = out; }

    k_prep<<<1024, 256>>>(x, y);
    k_cost<<<dim3(MM / 128, NN / 128), 256>>>(x, y);

    // iteration 1: exact two-pass (g = 0 -> column shift unsafe for fused form)
    k_row<<<NN / 2, 256>>>(p);
    k_colpart<<<512, 256>>>();
    k_colfin<<<16, 256>>>(q);

    // iterations 2..10: fused single-sweep
    for (int it = 1; it < ITERS; it++) {
        k_rowcol<<<FSLABS, 256>>>(p);
        k_colfin2<<<16, 256>>>(q);
    }

    k_final<<<2048, 256>>>(Pout, Pout != nullptr);
    if (costslot) k_costfin<<<1, 256>>>(costslot);
}